// round 2
// baseline (speedup 1.0000x reference)
#include <cuda_runtime.h>

// Problem constants
#define B_    32
#define N_    512
#define D_    1024
#define H_    16
#define HD_   64
#define SEG_  64
#define M_TOT (B_ * N_)          // 16384 rows for the big GEMMs
#define OUT_ELEMS   (M_TOT * D_) // 16,777,216 (output tensor)
#define ATTN_ELEMS  (B_ * H_ * N_ * SEG_) // 16,777,216 (attn tensor)

// Scratch (allocation-free): Q projection and received tensor
__device__ float g_q[M_TOT * D_];
__device__ float g_recv[M_TOT * D_];

// ---------------------------------------------------------------------------
// SGEMM: C[M,N] = A[M,K] @ B[K,N] + bias[N]    (all row-major, fp32)
// 128x128 block tile, BK=8, 256 threads, 8x8 per thread.
// M=16384, N=1024, K=1024 -> exact multiples, no bounds checks.
// ---------------------------------------------------------------------------
#define BM 128
#define BN 128
#define BK 8
#define TM 8
#define TN 8

__global__ __launch_bounds__(256) void sgemm_bias(
    const float* __restrict__ A, const float* __restrict__ Bm,
    const float* __restrict__ bias, float* __restrict__ C,
    int M, int N, int K)
{
    __shared__ float As[BK][BM];   // A tile transposed
    __shared__ float Bs[BK][BN];

    int tid = threadIdx.x;
    int row0 = blockIdx.y * BM;
    int col0 = blockIdx.x * BN;

    // A load: each thread one float4 (128 rows x 8 cols = 1024 floats)
    int a_row  = tid >> 1;          // 0..127
    int a_col4 = (tid & 1) * 4;     // 0 or 4
    // B load: each thread one float4 (8 rows x 128 cols)
    int b_row  = tid >> 5;          // 0..7
    int b_col4 = (tid & 31) * 4;    // 0..124

    const float* Aptr = A + (size_t)(row0 + a_row) * K + a_col4;
    const float* Bptr = Bm + (size_t)b_row * N + col0 + b_col4;

    int ty = tid >> 4, tx = tid & 15;
    float acc[TM][TN];
    #pragma unroll
    for (int i = 0; i < TM; i++)
        #pragma unroll
        for (int j = 0; j < TN; j++) acc[i][j] = 0.f;

    for (int k0 = 0; k0 < K; k0 += BK) {
        float4 av = *reinterpret_cast<const float4*>(Aptr + k0);
        As[a_col4 + 0][a_row] = av.x;
        As[a_col4 + 1][a_row] = av.y;
        As[a_col4 + 2][a_row] = av.z;
        As[a_col4 + 3][a_row] = av.w;
        float4 bv = *reinterpret_cast<const float4*>(Bptr + (size_t)k0 * N);
        *reinterpret_cast<float4*>(&Bs[b_row][b_col4]) = bv;
        __syncthreads();

        #pragma unroll
        for (int k = 0; k < BK; k++) {
            float ar[TM], br[TN];
            #pragma unroll
            for (int i = 0; i < TM; i++) ar[i] = As[k][ty * TM + i];
            #pragma unroll
            for (int j = 0; j < TN; j++) br[j] = Bs[k][tx * TN + j];
            #pragma unroll
            for (int i = 0; i < TM; i++)
                #pragma unroll
                for (int j = 0; j < TN; j++)
                    acc[i][j] += ar[i] * br[j];
        }
        __syncthreads();
    }

    #pragma unroll
    for (int i = 0; i < TM; i++) {
        int r = row0 + ty * TM + i;
        #pragma unroll
        for (int j = 0; j < TN; j += 4) {
            int c = col0 + tx * TN + j;
            float4 o;
            o.x = acc[i][j + 0] + bias[c + 0];
            o.y = acc[i][j + 1] + bias[c + 1];
            o.z = acc[i][j + 2] + bias[c + 2];
            o.w = acc[i][j + 3] + bias[c + 3];
            *reinterpret_cast<float4*>(C + (size_t)r * N + c) = o;
        }
    }
}

// ---------------------------------------------------------------------------
// Middle stage: per position n (one block each):
//   scores[b,h,n,s] = sum_d q[b,n,h*64+d] * router[s,n,d]
//   attn = softmax over s (64)
//   recv[b,n,h*64+d] = sum_s attn * router[s,n,d]
// 512 threads = 16 warps, warp w handles head h = w. Loop over b.
// ---------------------------------------------------------------------------
__global__ __launch_bounds__(512) void router_attn_kernel(
    const float* __restrict__ router,   // (SEG, N, HD)
    float* __restrict__ attn_out)       // (B, H, N, SEG) or nullptr
{
    __shared__ float rsm[SEG_][HD_ + 1];   // padded: conflict-free both axes
    __shared__ float qsm[D_];
    __shared__ float attn_sm[H_][SEG_];

    int n    = blockIdx.x;
    int tid  = threadIdx.x;
    int h    = tid >> 5;    // warp id == head id
    int lane = tid & 31;

    // Load router[:, n, :] slice (64x64) into padded smem
    for (int i = tid; i < SEG_ * HD_; i += 512) {
        int s = i >> 6, d = i & 63;
        rsm[s][d] = router[((size_t)s * N_ + n) * HD_ + d];
    }
    __syncthreads();

    for (int b = 0; b < B_; b++) {
        const float* qrow = g_q + ((size_t)b * N_ + n) * D_;
        qsm[tid]       = qrow[tid];
        qsm[tid + 512] = qrow[tid + 512];
        __syncthreads();

        // scores: lane handles s0 = lane, s1 = lane + 32
        int s0 = lane, s1 = lane + 32;
        float sc0 = 0.f, sc1 = 0.f;
        const float* qh = &qsm[h * HD_];
        #pragma unroll
        for (int d = 0; d < HD_; d++) {
            float qv = qh[d];
            sc0 += qv * rsm[s0][d];
            sc1 += qv * rsm[s1][d];
        }

        // softmax over the 64 scores (2 per lane) within the warp
        float m = fmaxf(sc0, sc1);
        #pragma unroll
        for (int o = 16; o > 0; o >>= 1)
            m = fmaxf(m, __shfl_xor_sync(0xffffffffu, m, o));
        float e0 = __expf(sc0 - m), e1 = __expf(sc1 - m);
        float sum = e0 + e1;
        #pragma unroll
        for (int o = 16; o > 0; o >>= 1)
            sum += __shfl_xor_sync(0xffffffffu, sum, o);
        float inv = 1.f / sum;
        float a0 = e0 * inv, a1 = e1 * inv;

        attn_sm[h][s0] = a0;
        attn_sm[h][s1] = a1;
        if (attn_out) {
            float* ap = attn_out + (((size_t)b * H_ + h) * N_ + n) * SEG_;
            ap[s0] = a0;
            ap[s1] = a1;
        }
        __syncwarp();

        // received: lane handles d0 = lane, d1 = lane + 32
        int d0 = lane, d1 = lane + 32;
        float r0 = 0.f, r1 = 0.f;
        #pragma unroll
        for (int s = 0; s < SEG_; s++) {
            float av = attn_sm[h][s];
            r0 += av * rsm[s][d0];
            r1 += av * rsm[s][d1];
        }
        float* rp = g_recv + ((size_t)b * N_ + n) * D_ + h * HD_;
        rp[d0] = r0;
        rp[d1] = r1;

        __syncthreads();   // qsm reused next b
    }
}

// ---------------------------------------------------------------------------
// Launch
// Inputs (metadata order): 0 query, 1 key, 2 value, 3 router,
//   4 Wq, 5 bq, 6 Wk, 7 bk, 8 Wv, 9 bv, 10 Wo, 11 bo
// Output: [output (B,N,D) | attn (B,H,N,SEG)]
// key/value/Wk/bk/Wv/bv are dead code in the reference -> skipped.
// ---------------------------------------------------------------------------
extern "C" void kernel_launch(void* const* d_in, const int* in_sizes, int n_in,
                              void* d_out, int out_size) {
    const float* query  = (const float*)d_in[0];
    const float* router = (const float*)d_in[3];
    const float* Wq     = (const float*)d_in[4];
    const float* bq     = (const float*)d_in[5];
    const float* Wo     = (const float*)d_in[10];
    const float* bo     = (const float*)d_in[11];
    float* out = (float*)d_out;

    float* qptr   = nullptr;
    float* rvptr  = nullptr;
    cudaGetSymbolAddress((void**)&qptr, g_q);
    cudaGetSymbolAddress((void**)&rvptr, g_recv);

    float* attn_out = (out_size >= (int)(OUT_ELEMS + ATTN_ELEMS))
                      ? out + OUT_ELEMS : nullptr;

    dim3 gemm_grid(D_ / BN, M_TOT / BM);   // (8, 128)

    // 1) Q projection
    sgemm_bias<<<gemm_grid, 256>>>(query, Wq, bq, qptr, M_TOT, D_, D_);
    // 2) router attention (scores -> softmax -> combine), writes attn + recv
    router_attn_kernel<<<N_, 512>>>(router, attn_out);
    // 3) output projection
    sgemm_bias<<<gemm_grid, 256>>>(rvptr, Wo, bo, out, M_TOT, D_, D_);
}

// round 4
// speedup vs baseline: 1.8795x; 1.8795x over previous
#include <cuda_runtime.h>
#include <cuda_bf16.h>
#include <cstdint>

// Problem constants
#define B_    32
#define N_    512
#define D_    1024
#define H_    16
#define HD_   64
#define SEG_  64
#define M_TOT (B_ * N_)                   // 16384
#define OUT_ELEMS   (M_TOT * D_)          // 16,777,216
#define ATTN_ELEMS  (B_ * H_ * N_ * SEG_) // 16,777,216

// -------- Scratch (allocation-free), 16B aligned for cp.async --------
__device__ __align__(16) float g_q[M_TOT * D_];
__device__ __align__(16) float g_recv[M_TOT * D_];
__device__ __align__(16) __nv_bfloat16 g_ahi[M_TOT * D_];
__device__ __align__(16) __nv_bfloat16 g_alo[M_TOT * D_];
__device__ __align__(16) __nv_bfloat16 g_wthi[D_ * D_];
__device__ __align__(16) __nv_bfloat16 g_wtlo[D_ * D_];

// ===========================================================================
// Helpers (baseline PTX only: works on .target sm_103 without 'a' features)
// ===========================================================================
__device__ __forceinline__ uint32_t smem_u32(const void* p) {
    uint32_t a;
    asm("{ .reg .u64 t; cvta.to.shared.u64 t, %1; cvt.u32.u64 %0, t; }"
        : "=r"(a) : "l"(p));
    return a;
}
__device__ __forceinline__ uint32_t lds32(uint32_t a) {
    uint32_t v;
    asm volatile("ld.shared.b32 %0, [%1];" : "=r"(v) : "r"(a));
    return v;
}
#define CP_ASYNC16(dst_u32, src_ptr) \
    asm volatile("cp.async.cg.shared.global [%0], [%1], 16;" \
                 :: "r"(dst_u32), "l"(src_ptr) : "memory")
#define CP_COMMIT() asm volatile("cp.async.commit_group;" ::: "memory")
#define CP_WAIT0()  asm volatile("cp.async.wait_group 0;" ::: "memory")

// m16n8k16 bf16 MMA, fp32 accumulate (A row-major, B col-major)
__device__ __forceinline__ void mma16816(float* c, const uint32_t* a, const uint32_t* b) {
    asm volatile(
        "mma.sync.aligned.m16n8k16.row.col.f32.bf16.bf16.f32 "
        "{%0,%1,%2,%3}, {%4,%5,%6,%7}, {%8,%9}, {%0,%1,%2,%3};"
        : "+f"(c[0]), "+f"(c[1]), "+f"(c[2]), "+f"(c[3])
        : "r"(a[0]), "r"(a[1]), "r"(a[2]), "r"(a[3]), "r"(b[0]), "r"(b[1]));
}

// ===========================================================================
// Conversion kernels
// ===========================================================================
__global__ __launch_bounds__(256) void split_kernel(
    const float* __restrict__ x, __nv_bfloat16* __restrict__ hi,
    __nv_bfloat16* __restrict__ lo, int n4)
{
    int i = blockIdx.x * blockDim.x + threadIdx.x;
    if (i >= n4) return;
    float4 v = reinterpret_cast<const float4*>(x)[i];
    union { __nv_bfloat16 h[4]; uint2 u; } ph, pl;
    float vv[4] = {v.x, v.y, v.z, v.w};
    #pragma unroll
    for (int j = 0; j < 4; j++) {
        __nv_bfloat16 h = __float2bfloat16(vv[j]);
        ph.h[j] = h;
        pl.h[j] = __float2bfloat16(vv[j] - __bfloat162float(h));
    }
    reinterpret_cast<uint2*>(hi)[i] = ph.u;
    reinterpret_cast<uint2*>(lo)[i] = pl.u;
}

// W[K][N] fp32 -> Wt_hi/lo[N][K] bf16 (transpose + split)
__global__ __launch_bounds__(256) void transpose_split(
    const float* __restrict__ W, __nv_bfloat16* __restrict__ Thi,
    __nv_bfloat16* __restrict__ Tlo)
{
    __shared__ float tile[32][33];
    int nx = blockIdx.x * 32 + threadIdx.x;
    #pragma unroll
    for (int i = 0; i < 4; i++) {
        int ky = blockIdx.y * 32 + threadIdx.y + i * 8;
        tile[threadIdx.y + i * 8][threadIdx.x] = W[(size_t)ky * D_ + nx];
    }
    __syncthreads();
    int ko = blockIdx.y * 32 + threadIdx.x;
    #pragma unroll
    for (int i = 0; i < 4; i++) {
        int no = blockIdx.x * 32 + threadIdx.y + i * 8;
        float v = tile[threadIdx.x][threadIdx.y + i * 8];
        __nv_bfloat16 h = __float2bfloat16(v);
        size_t idx = (size_t)no * D_ + ko;
        Thi[idx] = h;
        Tlo[idx] = __float2bfloat16(v - __bfloat162float(h));
    }
}

// ===========================================================================
// Tensor-core GEMM via mma.sync (HMMA):
//   C[M,1024] = (Ahi+Alo)[M,1024] @ Wt^T + bias,  Wt stored [N][K] (k-contig)
// 128x128 CTA tile, 8 warps (2m x 4n), 64x32 per warp.
// K-chunks of 16, double-buffered cp.async. 3 MMA terms: hh + hl + lh.
// Smem: 4 mats x 128 rows x 24 bf16 (pad 16->24, 48B pitch) x 2 bufs = 48KB.
// ===========================================================================
#define KC      16
#define NCH     (D_ / KC)        // 64
#define SKB     48               // smem row pitch bytes (24 bf16)
#define MAT_B   (128 * SKB)      // 6144
#define BUF_B   (4 * MAT_B)      // 24576
#define SMEM_SZ (2 * BUF_B)      // 49152 == default 48KB dynamic limit

__global__ __launch_bounds__(256) void gemm_mma(
    const __nv_bfloat16* __restrict__ Ahi, const __nv_bfloat16* __restrict__ Alo,
    const __nv_bfloat16* __restrict__ Bhi, const __nv_bfloat16* __restrict__ Blo,
    const float* __restrict__ bias, float* __restrict__ C)
{
    extern __shared__ __align__(16) char smem[];
    const uint32_t sb = smem_u32(smem);
    const int tid  = threadIdx.x;
    const int wid  = tid >> 5;
    const int lane = tid & 31;
    const int warp_m = wid & 1;          // 0..1  -> m offset 0/64
    const int warp_n = wid >> 1;         // 0..3  -> n offset 0/32/64/96
    const int row0 = blockIdx.y * 128;
    const int col0 = blockIdx.x * 128;
    const int g    = lane >> 2;          // groupID 0..7
    const int tg4  = (lane & 3) * 4;     // byte offset of k-pair within row

    const __nv_bfloat16* mats[4] = {Ahi, Alo, Bhi, Blo};

    float acc[4][4][4];
    #pragma unroll
    for (int mt = 0; mt < 4; mt++)
        #pragma unroll
        for (int nt = 0; nt < 4; nt++)
            #pragma unroll
            for (int j = 0; j < 4; j++) acc[mt][nt][j] = 0.f;

    // ---- cp.async one K-chunk (16 cols) of all 4 matrices into buffer ----
    // per matrix: 128 rows x 32B = 256 x 16B transfers; 256 threads -> 1 each
    const int ld_r = tid >> 1;           // 0..127
    const int ld_c = (tid & 1) * 16;     // byte 0 or 16 within 32B row
    auto issue_chunk = [&](int kc, int buf) {
        const int k0 = kc * KC;
        const uint32_t sbase = sb + buf * BUF_B;
        #pragma unroll
        for (int m = 0; m < 4; m++) {
            const int base0 = (m < 2) ? row0 : col0;
            const __nv_bfloat16* src =
                mats[m] + (size_t)(base0 + ld_r) * D_ + k0 + (ld_c >> 1);
            CP_ASYNC16(sbase + m * MAT_B + ld_r * SKB + ld_c, src);
        }
    };

    // ---- compute one K-chunk (one k16 step) ----
    auto compute_chunk = [&](int buf) {
        const uint32_t sbase = sb + buf * BUF_B;
        const uint32_t aH = sbase;
        const uint32_t aL = sbase + MAT_B;
        const uint32_t bH = sbase + 2 * MAT_B;
        const uint32_t bL = sbase + 3 * MAT_B;

        uint32_t ah[4][4], al[4][4], bh[4][2], bl[4][2];
        #pragma unroll
        for (int mt = 0; mt < 4; mt++) {
            uint32_t off = (uint32_t)(warp_m * 64 + mt * 16 + g) * SKB + tg4;
            ah[mt][0] = lds32(aH + off);
            ah[mt][1] = lds32(aH + off + 8 * SKB);
            ah[mt][2] = lds32(aH + off + 16);
            ah[mt][3] = lds32(aH + off + 8 * SKB + 16);
            al[mt][0] = lds32(aL + off);
            al[mt][1] = lds32(aL + off + 8 * SKB);
            al[mt][2] = lds32(aL + off + 16);
            al[mt][3] = lds32(aL + off + 8 * SKB + 16);
        }
        #pragma unroll
        for (int nt = 0; nt < 4; nt++) {
            uint32_t off = (uint32_t)(warp_n * 32 + nt * 8 + g) * SKB + tg4;
            bh[nt][0] = lds32(bH + off);
            bh[nt][1] = lds32(bH + off + 16);
            bl[nt][0] = lds32(bL + off);
            bl[nt][1] = lds32(bL + off + 16);
        }
        #pragma unroll
        for (int mt = 0; mt < 4; mt++)
            #pragma unroll
            for (int nt = 0; nt < 4; nt++) {
                mma16816(acc[mt][nt], ah[mt], bh[nt]);
                mma16816(acc[mt][nt], ah[mt], bl[nt]);
                mma16816(acc[mt][nt], al[mt], bh[nt]);
            }
    };

    // ---- pipeline ----
    issue_chunk(0, 0);
    CP_COMMIT();
    for (int i = 0; i < NCH; i++) {
        CP_WAIT0();
        __syncthreads();               // chunk i visible; prior compute done
        if (i + 1 < NCH) { issue_chunk(i + 1, (i + 1) & 1); CP_COMMIT(); }
        compute_chunk(i & 1);
    }

    // ---- epilogue: add bias, store fp32 ----
    const int cbase = col0 + warp_n * 32 + (lane & 3) * 2;
    #pragma unroll
    for (int mt = 0; mt < 4; mt++) {
        int r = row0 + warp_m * 64 + mt * 16 + g;
        #pragma unroll
        for (int nt = 0; nt < 4; nt++) {
            int c = cbase + nt * 8;
            float2 bv = *reinterpret_cast<const float2*>(bias + c);
            float2 o0 = make_float2(acc[mt][nt][0] + bv.x, acc[mt][nt][1] + bv.y);
            float2 o1 = make_float2(acc[mt][nt][2] + bv.x, acc[mt][nt][3] + bv.y);
            *reinterpret_cast<float2*>(C + (size_t)r * D_ + c) = o0;
            *reinterpret_cast<float2*>(C + (size_t)(r + 8) * D_ + c) = o1;
        }
    }
}

// ===========================================================================
// Middle stage: per (position n, batch-chunk) block. 512 thr = 16 warps = heads.
// ===========================================================================
#define BCHUNK 8
__global__ __launch_bounds__(512) void router_attn_kernel(
    const float* __restrict__ router,   // (SEG, N, HD)
    float* __restrict__ attn_out)       // (B, H, N, SEG) or nullptr
{
    __shared__ float rsm[SEG_][HD_ + 1];
    __shared__ float qsm[D_];
    __shared__ float attn_sm[H_][SEG_];

    int n    = blockIdx.x;
    int b0c  = blockIdx.y * BCHUNK;
    int tid  = threadIdx.x;
    int h    = tid >> 5;
    int lane = tid & 31;

    for (int i = tid; i < SEG_ * HD_; i += 512) {
        int s = i >> 6, d = i & 63;
        rsm[s][d] = router[((size_t)s * N_ + n) * HD_ + d];
    }
    __syncthreads();

    for (int b = b0c; b < b0c + BCHUNK; b++) {
        const float* qrow = g_q + ((size_t)b * N_ + n) * D_;
        qsm[tid]       = qrow[tid];
        qsm[tid + 512] = qrow[tid + 512];
        __syncthreads();

        int s0 = lane, s1 = lane + 32;
        float sc0 = 0.f, sc1 = 0.f;
        const float* qh = &qsm[h * HD_];
        #pragma unroll
        for (int d = 0; d < HD_; d++) {
            float qv = qh[d];
            sc0 += qv * rsm[s0][d];
            sc1 += qv * rsm[s1][d];
        }

        float m = fmaxf(sc0, sc1);
        #pragma unroll
        for (int o = 16; o > 0; o >>= 1)
            m = fmaxf(m, __shfl_xor_sync(0xffffffffu, m, o));
        float e0 = __expf(sc0 - m), e1 = __expf(sc1 - m);
        float sum = e0 + e1;
        #pragma unroll
        for (int o = 16; o > 0; o >>= 1)
            sum += __shfl_xor_sync(0xffffffffu, sum, o);
        float inv = 1.f / sum;
        float a0 = e0 * inv, a1 = e1 * inv;

        attn_sm[h][s0] = a0;
        attn_sm[h][s1] = a1;
        if (attn_out) {
            float* ap = attn_out + (((size_t)b * H_ + h) * N_ + n) * SEG_;
            ap[s0] = a0;
            ap[s1] = a1;
        }
        __syncwarp();

        int d0 = lane, d1 = lane + 32;
        float r0 = 0.f, r1 = 0.f;
        #pragma unroll
        for (int s = 0; s < SEG_; s++) {
            float av = attn_sm[h][s];
            r0 += av * rsm[s][d0];
            r1 += av * rsm[s][d1];
        }
        float* rp = g_recv + ((size_t)b * N_ + n) * D_ + h * HD_;
        rp[d0] = r0;
        rp[d1] = r1;

        __syncthreads();
    }
}

// ===========================================================================
// Launch
// ===========================================================================
extern "C" void kernel_launch(void* const* d_in, const int* in_sizes, int n_in,
                              void* d_out, int out_size) {
    const float* query  = (const float*)d_in[0];
    const float* router = (const float*)d_in[3];
    const float* Wq     = (const float*)d_in[4];
    const float* bq     = (const float*)d_in[5];
    const float* Wo     = (const float*)d_in[10];
    const float* bo     = (const float*)d_in[11];
    float* out = (float*)d_out;

    float *qptr, *rvptr;
    __nv_bfloat16 *ahi, *alo, *wthi, *wtlo;
    cudaGetSymbolAddress((void**)&qptr,  g_q);
    cudaGetSymbolAddress((void**)&rvptr, g_recv);
    cudaGetSymbolAddress((void**)&ahi,   g_ahi);
    cudaGetSymbolAddress((void**)&alo,   g_alo);
    cudaGetSymbolAddress((void**)&wthi,  g_wthi);
    cudaGetSymbolAddress((void**)&wtlo,  g_wtlo);

    float* attn_out = (out_size >= (int)(OUT_ELEMS + ATTN_ELEMS))
                      ? out + OUT_ELEMS : nullptr;

    dim3 tgrid(32, 32), tblk(32, 8);
    dim3 ggrid(D_ / 128, M_TOT / 128);   // (8, 128)
    int n4 = OUT_ELEMS / 4;

    // 1) Q = query @ Wq + bq
    split_kernel<<<(n4 + 255) / 256, 256>>>(query, ahi, alo, n4);
    transpose_split<<<tgrid, tblk>>>(Wq, wthi, wtlo);
    gemm_mma<<<ggrid, 256, SMEM_SZ>>>(ahi, alo, wthi, wtlo, bq, qptr);

    // 2) router attention
    router_attn_kernel<<<dim3(N_, B_ / BCHUNK), 512>>>(router, attn_out);

    // 3) output = recv @ Wo + bo
    split_kernel<<<(n4 + 255) / 256, 256>>>(rvptr, ahi, alo, n4);
    transpose_split<<<tgrid, tblk>>>(Wo, wthi, wtlo);
    gemm_mma<<<ggrid, 256, SMEM_SZ>>>(ahi, alo, wthi, wtlo, bo, out);
}

// round 9
// speedup vs baseline: 2.7801x; 1.4792x over previous
#include <cuda_runtime.h>
#include <cuda_bf16.h>
#include <cstdint>

// Problem constants
#define B_    32
#define N_    512
#define D_    1024
#define H_    16
#define HD_   64
#define SEG_  64
#define M_TOT (B_ * N_)                   // 16384
#define OUT_ELEMS   (M_TOT * D_)          // 16,777,216
#define ATTN_ELEMS  (B_ * H_ * N_ * SEG_) // 16,777,216

// -------- Scratch (allocation-free), 16B aligned --------
__device__ __align__(16) __nv_bfloat16 g_ahi[M_TOT * D_];   // A-split / recv-split
__device__ __align__(16) __nv_bfloat16 g_alo[M_TOT * D_];
__device__ __align__(16) __nv_bfloat16 g_qhi[M_TOT * D_];   // q-split (gemm1 out)
__device__ __align__(16) __nv_bfloat16 g_qlo[M_TOT * D_];
__device__ __align__(16) __nv_bfloat16 g_wthi[D_ * D_];
__device__ __align__(16) __nv_bfloat16 g_wtlo[D_ * D_];

// ===========================================================================
// Helpers (baseline PTX only — no sm_103a-gated features)
// ===========================================================================
__device__ __forceinline__ uint32_t smem_u32(const void* p) {
    uint32_t a;
    asm("{ .reg .u64 t; cvta.to.shared.u64 t, %1; cvt.u32.u64 %0, t; }"
        : "=r"(a) : "l"(p));
    return a;
}
#define CP_ASYNC16(dst_u32, src_ptr) \
    asm volatile("cp.async.cg.shared.global [%0], [%1], 16;" \
                 :: "r"(dst_u32), "l"(src_ptr) : "memory")
#define CP_COMMIT() asm volatile("cp.async.commit_group;" ::: "memory")
#define CP_WAIT0()  asm volatile("cp.async.wait_group 0;" ::: "memory")

__device__ __forceinline__ void ldsm_x4(uint32_t* r, uint32_t addr) {
    asm volatile("ldmatrix.sync.aligned.m8n8.x4.shared.b16 {%0,%1,%2,%3}, [%4];"
                 : "=r"(r[0]), "=r"(r[1]), "=r"(r[2]), "=r"(r[3]) : "r"(addr));
}
__device__ __forceinline__ void ldsm_x2(uint32_t* r, uint32_t addr) {
    asm volatile("ldmatrix.sync.aligned.m8n8.x2.shared.b16 {%0,%1}, [%2];"
                 : "=r"(r[0]), "=r"(r[1]) : "r"(addr));
}
__device__ __forceinline__ void ldsm_x2t(uint32_t* r, uint32_t addr) {
    asm volatile("ldmatrix.sync.aligned.m8n8.x2.trans.shared.b16 {%0,%1}, [%2];"
                 : "=r"(r[0]), "=r"(r[1]) : "r"(addr));
}

// m16n8k16 bf16 MMA, fp32 accumulate
__device__ __forceinline__ void mma16816(float* c, const uint32_t* a, const uint32_t* b) {
    asm volatile(
        "mma.sync.aligned.m16n8k16.row.col.f32.bf16.bf16.f32 "
        "{%0,%1,%2,%3}, {%4,%5,%6,%7}, {%8,%9}, {%0,%1,%2,%3};"
        : "+f"(c[0]), "+f"(c[1]), "+f"(c[2]), "+f"(c[3])
        : "r"(a[0]), "r"(a[1]), "r"(a[2]), "r"(a[3]), "r"(b[0]), "r"(b[1]));
}

// split a float pair into packed bf16 hi + lo residual words
__device__ __forceinline__ void split2(float x, float y, uint32_t& hi, uint32_t& lo) {
    __nv_bfloat16 hx = __float2bfloat16(x), hy = __float2bfloat16(y);
    __nv_bfloat162 h2, l2;
    h2.x = hx; h2.y = hy;
    l2.x = __float2bfloat16(x - __bfloat162float(hx));
    l2.y = __float2bfloat16(y - __bfloat162float(hy));
    hi = *reinterpret_cast<uint32_t*>(&h2);
    lo = *reinterpret_cast<uint32_t*>(&l2);
}

// ===========================================================================
// Conversion kernels
// ===========================================================================
__global__ __launch_bounds__(256) void split_kernel(
    const float* __restrict__ x, __nv_bfloat16* __restrict__ hi,
    __nv_bfloat16* __restrict__ lo, int n4)
{
    int i = blockIdx.x * blockDim.x + threadIdx.x;
    if (i >= n4) return;
    float4 v = reinterpret_cast<const float4*>(x)[i];
    uint32_t h01, l01, h23, l23;
    split2(v.x, v.y, h01, l01);
    split2(v.z, v.w, h23, l23);
    reinterpret_cast<uint2*>(hi)[i] = make_uint2(h01, h23);
    reinterpret_cast<uint2*>(lo)[i] = make_uint2(l01, l23);
}

// W[K][N] fp32 -> Wt_hi/lo[N][K] bf16 (transpose + split)
__global__ __launch_bounds__(256) void transpose_split(
    const float* __restrict__ W, __nv_bfloat16* __restrict__ Thi,
    __nv_bfloat16* __restrict__ Tlo)
{
    __shared__ float tile[32][33];
    int nx = blockIdx.x * 32 + threadIdx.x;
    #pragma unroll
    for (int i = 0; i < 4; i++) {
        int ky = blockIdx.y * 32 + threadIdx.y + i * 8;
        tile[threadIdx.y + i * 8][threadIdx.x] = W[(size_t)ky * D_ + nx];
    }
    __syncthreads();
    int ko = blockIdx.y * 32 + threadIdx.x;
    #pragma unroll
    for (int i = 0; i < 4; i++) {
        int no = blockIdx.x * 32 + threadIdx.y + i * 8;
        float v = tile[threadIdx.x][threadIdx.y + i * 8];
        __nv_bfloat16 h = __float2bfloat16(v);
        size_t idx = (size_t)no * D_ + ko;
        Thi[idx] = h;
        Tlo[idx] = __float2bfloat16(v - __bfloat162float(h));
    }
}

// ===========================================================================
// Tensor-core GEMM (HMMA + ldmatrix):
//   C[M,1024] = (Ahi+Alo) @ Wt^T + bias,  Wt stored [N][K]
// Output: fp32 (Cf) OR split bf16 (Chi/Clo).
// ===========================================================================
#define KC      16
#define NCH     (D_ / KC)        // 64
#define SKB     48               // smem row pitch bytes
#define MAT_B   (128 * SKB)
#define BUF_B   (4 * MAT_B)
#define SMEM_SZ (2 * BUF_B)      // 49152

__global__ __launch_bounds__(256) void gemm_mma(
    const __nv_bfloat16* __restrict__ Ahi, const __nv_bfloat16* __restrict__ Alo,
    const __nv_bfloat16* __restrict__ Bhi, const __nv_bfloat16* __restrict__ Blo,
    const float* __restrict__ bias, float* __restrict__ Cf,
    __nv_bfloat16* __restrict__ Chi, __nv_bfloat16* __restrict__ Clo)
{
    extern __shared__ __align__(16) char smem[];
    const uint32_t sb = smem_u32(smem);
    const int tid  = threadIdx.x;
    const int wid  = tid >> 5;
    const int lane = tid & 31;
    const int warp_m = wid & 1;
    const int warp_n = wid >> 1;
    const int row0 = blockIdx.y * 128;
    const int col0 = blockIdx.x * 128;
    const int g    = lane >> 2;
    // ldmatrix lane-address components
    const uint32_t a_lrow = (uint32_t)(warp_m * 64 + (lane & 15)) * SKB + ((lane >> 4) * 16);
    const uint32_t b_lrow = (uint32_t)(warp_n * 32 + (lane & 7)) * SKB + (((lane >> 3) & 1) * 16);

    const __nv_bfloat16* mats[4] = {Ahi, Alo, Bhi, Blo};

    float acc[4][4][4];
    #pragma unroll
    for (int mt = 0; mt < 4; mt++)
        #pragma unroll
        for (int nt = 0; nt < 4; nt++)
            #pragma unroll
            for (int j = 0; j < 4; j++) acc[mt][nt][j] = 0.f;

    const int ld_r = tid >> 1;
    const int ld_c = (tid & 1) * 16;
    auto issue_chunk = [&](int kc, int buf) {
        const int k0 = kc * KC;
        const uint32_t sbase = sb + buf * BUF_B;
        #pragma unroll
        for (int m = 0; m < 4; m++) {
            const int base0 = (m < 2) ? row0 : col0;
            const __nv_bfloat16* src =
                mats[m] + (size_t)(base0 + ld_r) * D_ + k0 + (ld_c >> 1);
            CP_ASYNC16(sbase + m * MAT_B + ld_r * SKB + ld_c, src);
        }
    };

    auto compute_chunk = [&](int buf) {
        const uint32_t sbase = sb + buf * BUF_B;
        uint32_t ah[4][4], al[4][4], bh[4][2], bl[4][2];
        #pragma unroll
        for (int mt = 0; mt < 4; mt++) {
            ldsm_x4(ah[mt], sbase + 0 * MAT_B + a_lrow + mt * 16 * SKB);
            ldsm_x4(al[mt], sbase + 1 * MAT_B + a_lrow + mt * 16 * SKB);
        }
        #pragma unroll
        for (int nt = 0; nt < 4; nt++) {
            ldsm_x2(bh[nt], sbase + 2 * MAT_B + b_lrow + nt * 8 * SKB);
            ldsm_x2(bl[nt], sbase + 3 * MAT_B + b_lrow + nt * 8 * SKB);
        }
        #pragma unroll
        for (int mt = 0; mt < 4; mt++)
            #pragma unroll
            for (int nt = 0; nt < 4; nt++) {
                mma16816(acc[mt][nt], ah[mt], bh[nt]);
                mma16816(acc[mt][nt], ah[mt], bl[nt]);
                mma16816(acc[mt][nt], al[mt], bh[nt]);
            }
    };

    issue_chunk(0, 0);
    CP_COMMIT();
    for (int i = 0; i < NCH; i++) {
        CP_WAIT0();
        __syncthreads();
        if (i + 1 < NCH) { issue_chunk(i + 1, (i + 1) & 1); CP_COMMIT(); }
        compute_chunk(i & 1);
    }

    // ---- epilogue ----
    const int cbase = col0 + warp_n * 32 + (lane & 3) * 2;
    #pragma unroll
    for (int mt = 0; mt < 4; mt++) {
        int r = row0 + warp_m * 64 + mt * 16 + g;
        #pragma unroll
        for (int nt = 0; nt < 4; nt++) {
            int c = cbase + nt * 8;
            float2 bv = *reinterpret_cast<const float2*>(bias + c);
            float x0 = acc[mt][nt][0] + bv.x, y0 = acc[mt][nt][1] + bv.y;
            float x1 = acc[mt][nt][2] + bv.x, y1 = acc[mt][nt][3] + bv.y;
            if (Cf) {
                *reinterpret_cast<float2*>(Cf + (size_t)r * D_ + c) = make_float2(x0, y0);
                *reinterpret_cast<float2*>(Cf + (size_t)(r + 8) * D_ + c) = make_float2(x1, y1);
            } else {
                uint32_t h0, l0, h1, l1;
                split2(x0, y0, h0, l0);
                split2(x1, y1, h1, l1);
                *reinterpret_cast<uint32_t*>(Chi + (size_t)r * D_ + c) = h0;
                *reinterpret_cast<uint32_t*>(Clo + (size_t)r * D_ + c) = l0;
                *reinterpret_cast<uint32_t*>(Chi + (size_t)(r + 8) * D_ + c) = h1;
                *reinterpret_cast<uint32_t*>(Clo + (size_t)(r + 8) * D_ + c) = l1;
            }
        }
    }
}

// ===========================================================================
// Middle stage, tensor cores. Block = (n, m-tile of 64 (b,h) rows), 4 warps.
//   S = Qm @ R_n^T (split 3-MMA, fp32)  -> softmax in fragment layout
//   attn -> global fp32; recv = attn @ R_n (split 3-MMA) -> split bf16 out
// Smem: Qhi/Qlo (64x64) + Rhi/Rlo (64x64), pitch 144B (conflict-free ldmatrix)
// ===========================================================================
#define RP    144
#define RMAT  (64 * RP)          // 9216
#define RQHI  0
#define RQLO  RMAT
#define RRHI  (2 * RMAT)
#define RRLO  (3 * RMAT)
#define RSMEM (4 * RMAT)         // 36864

__global__ __launch_bounds__(128) void router_mma(
    const float* __restrict__ router,          // (SEG, N, HD) fp32
    const __nv_bfloat16* __restrict__ Qhi, const __nv_bfloat16* __restrict__ Qlo,
    float* __restrict__ attn_out,              // (B,H,N,SEG) or nullptr
    __nv_bfloat16* __restrict__ Rvhi, __nv_bfloat16* __restrict__ Rvlo)
{
    extern __shared__ __align__(16) char rs[];
    const uint32_t sb = smem_u32(rs);
    const int n   = blockIdx.x;
    const int mt  = blockIdx.y;        // m-tile: rows mt*64 .. +63 over (b*H+h)
    const int tid = threadIdx.x;
    const int w   = tid >> 5;
    const int lane = tid & 31;
    const int g   = lane >> 2;
    const int tg  = lane & 3;

    // ---- load + split router slice R_n (64 s x 64 d) ----
    for (int idx = tid; idx < SEG_ * 16; idx += 128) {
        int s = idx >> 4, d4 = (idx & 15) * 4;
        float4 v = *reinterpret_cast<const float4*>(
            router + ((size_t)s * N_ + n) * HD_ + d4);
        uint32_t h01, l01, h23, l23;
        split2(v.x, v.y, h01, l01);
        split2(v.z, v.w, h23, l23);
        uint32_t off = s * RP + d4 * 2;
        *reinterpret_cast<uint32_t*>(rs + RRHI + off)     = h01;
        *reinterpret_cast<uint32_t*>(rs + RRHI + off + 4) = h23;
        *reinterpret_cast<uint32_t*>(rs + RRLO + off)     = l01;
        *reinterpret_cast<uint32_t*>(rs + RRLO + off + 4) = l23;
    }
    // ---- load Q tile (64 rows x 64 d, hi/lo) ----
    for (int idx = tid; idx < 64 * 8; idx += 128) {
        int r = idx >> 3, c8 = (idx & 7) * 8;
        int mg = mt * 64 + r;
        size_t gbase = ((size_t)(mg >> 4) * N_ + n) * D_ + (mg & 15) * HD_ + c8;
        *reinterpret_cast<uint4*>(rs + RQHI + r * RP + c8 * 2) =
            *reinterpret_cast<const uint4*>(Qhi + gbase);
        *reinterpret_cast<uint4*>(rs + RQLO + r * RP + c8 * 2) =
            *reinterpret_cast<const uint4*>(Qlo + gbase);
    }
    __syncthreads();

    // ---- scores: S[j][0..3], j = n-tile over s ----
    float S[8][4];
    #pragma unroll
    for (int j = 0; j < 8; j++)
        #pragma unroll
        for (int q = 0; q < 4; q++) S[j][q] = 0.f;

    const uint32_t a_lrow = (uint32_t)(w * 16 + (lane & 15)) * RP + ((lane >> 4) * 16);
    const uint32_t b_lrow = (uint32_t)(lane & 7) * RP + (((lane >> 3) & 1) * 16);

    #pragma unroll
    for (int t = 0; t < 4; t++) {
        uint32_t ah[4], al[4];
        ldsm_x4(ah, sb + RQHI + a_lrow + t * 32);
        ldsm_x4(al, sb + RQLO + a_lrow + t * 32);
        #pragma unroll
        for (int j = 0; j < 8; j++) {
            uint32_t bh[2], bl[2];
            ldsm_x2(bh, sb + RRHI + b_lrow + j * 8 * RP + t * 32);
            ldsm_x2(bl, sb + RRLO + b_lrow + j * 8 * RP + t * 32);
            mma16816(S[j], ah, bh);
            mma16816(S[j], ah, bl);
            mma16816(S[j], al, bh);
        }
    }

    // ---- softmax over s (64), rows g and g+8; reduce across quad lanes ----
    float m0 = S[0][0], m1 = S[0][2];
    #pragma unroll
    for (int j = 0; j < 8; j++) {
        m0 = fmaxf(m0, fmaxf(S[j][0], S[j][1]));
        m1 = fmaxf(m1, fmaxf(S[j][2], S[j][3]));
    }
    m0 = fmaxf(m0, __shfl_xor_sync(0xffffffffu, m0, 1));
    m0 = fmaxf(m0, __shfl_xor_sync(0xffffffffu, m0, 2));
    m1 = fmaxf(m1, __shfl_xor_sync(0xffffffffu, m1, 1));
    m1 = fmaxf(m1, __shfl_xor_sync(0xffffffffu, m1, 2));
    float s0 = 0.f, s1 = 0.f;
    #pragma unroll
    for (int j = 0; j < 8; j++) {
        S[j][0] = __expf(S[j][0] - m0); s0 += S[j][0];
        S[j][1] = __expf(S[j][1] - m0); s0 += S[j][1];
        S[j][2] = __expf(S[j][2] - m1); s1 += S[j][2];
        S[j][3] = __expf(S[j][3] - m1); s1 += S[j][3];
    }
    s0 += __shfl_xor_sync(0xffffffffu, s0, 1);
    s0 += __shfl_xor_sync(0xffffffffu, s0, 2);
    s1 += __shfl_xor_sync(0xffffffffu, s1, 1);
    s1 += __shfl_xor_sync(0xffffffffu, s1, 2);
    float inv0 = 1.f / s0, inv1 = 1.f / s1;
    #pragma unroll
    for (int j = 0; j < 8; j++) {
        S[j][0] *= inv0; S[j][1] *= inv0;
        S[j][2] *= inv1; S[j][3] *= inv1;
    }

    const int mg0 = mt * 64 + w * 16 + g;
    const int mg1 = mg0 + 8;

    // ---- store attn (fp32) ----
    if (attn_out) {
        float* a0p = attn_out + ((size_t)mg0 * N_ + n) * SEG_ + tg * 2;
        float* a1p = attn_out + ((size_t)mg1 * N_ + n) * SEG_ + tg * 2;
        #pragma unroll
        for (int j = 0; j < 8; j++) {
            *reinterpret_cast<float2*>(a0p + j * 8) = make_float2(S[j][0], S[j][1]);
            *reinterpret_cast<float2*>(a1p + j * 8) = make_float2(S[j][2], S[j][3]);
        }
    }

    // ---- recv = attn @ R_n: attn accum regs become A-frags; B via ldmatrix.trans ----
    float O[8][4];
    #pragma unroll
    for (int j = 0; j < 8; j++)
        #pragma unroll
        for (int q = 0; q < 4; q++) O[j][q] = 0.f;

    const uint32_t bt_lrow = (uint32_t)(lane & 15) * RP;   // k(=s) rows for trans load
    #pragma unroll
    for (int t = 0; t < 4; t++) {
        uint32_t fh[4], fl[4];
        split2(S[2*t][0],   S[2*t][1],   fh[0], fl[0]);
        split2(S[2*t][2],   S[2*t][3],   fh[1], fl[1]);
        split2(S[2*t+1][0], S[2*t+1][1], fh[2], fl[2]);
        split2(S[2*t+1][2], S[2*t+1][3], fh[3], fl[3]);
        #pragma unroll
        for (int j = 0; j < 8; j++) {
            uint32_t bh[2], bl[2];
            ldsm_x2t(bh, sb + RRHI + (t * 16) * RP + bt_lrow + j * 16);
            ldsm_x2t(bl, sb + RRLO + (t * 16) * RP + bt_lrow + j * 16);
            mma16816(O[j], fh, bh);
            mma16816(O[j], fh, bl);
            mma16816(O[j], fl, bh);
        }
    }

    // ---- store recv as split bf16 into g_ahi/g_alo layout (b*N+n, h*64+d) ----
    size_t r0base = ((size_t)(mg0 >> 4) * N_ + n) * D_ + (mg0 & 15) * HD_ + tg * 2;
    size_t r1base = ((size_t)(mg1 >> 4) * N_ + n) * D_ + (mg1 & 15) * HD_ + tg * 2;
    #pragma unroll
    for (int j = 0; j < 8; j++) {
        uint32_t h0, l0, h1, l1;
        split2(O[j][0], O[j][1], h0, l0);
        split2(O[j][2], O[j][3], h1, l1);
        *reinterpret_cast<uint32_t*>(Rvhi + r0base + j * 8) = h0;
        *reinterpret_cast<uint32_t*>(Rvlo + r0base + j * 8) = l0;
        *reinterpret_cast<uint32_t*>(Rvhi + r1base + j * 8) = h1;
        *reinterpret_cast<uint32_t*>(Rvlo + r1base + j * 8) = l1;
    }
}

// ===========================================================================
// Launch
// ===========================================================================
extern "C" void kernel_launch(void* const* d_in, const int* in_sizes, int n_in,
                              void* d_out, int out_size) {
    const float* query  = (const float*)d_in[0];
    const float* router = (const float*)d_in[3];
    const float* Wq     = (const float*)d_in[4];
    const float* bq     = (const float*)d_in[5];
    const float* Wo     = (const float*)d_in[10];
    const float* bo     = (const float*)d_in[11];
    float* out = (float*)d_out;

    __nv_bfloat16 *ahi, *alo, *qhi, *qlo, *wthi, *wtlo;
    cudaGetSymbolAddress((void**)&ahi,  g_ahi);
    cudaGetSymbolAddress((void**)&alo,  g_alo);
    cudaGetSymbolAddress((void**)&qhi,  g_qhi);
    cudaGetSymbolAddress((void**)&qlo,  g_qlo);
    cudaGetSymbolAddress((void**)&wthi, g_wthi);
    cudaGetSymbolAddress((void**)&wtlo, g_wtlo);

    float* attn_out = (out_size >= (int)(OUT_ELEMS + ATTN_ELEMS))
                      ? out + OUT_ELEMS : nullptr;

    dim3 tgrid(32, 32), tblk(32, 8);
    dim3 ggrid(D_ / 128, M_TOT / 128);
    int n4 = OUT_ELEMS / 4;

    // 1) Q = query @ Wq + bq  -> split bf16 directly
    split_kernel<<<(n4 + 255) / 256, 256>>>(query, ahi, alo, n4);
    transpose_split<<<tgrid, tblk>>>(Wq, wthi, wtlo);
    gemm_mma<<<ggrid, 256, SMEM_SZ>>>(ahi, alo, wthi, wtlo, bq,
                                      nullptr, qhi, qlo);

    // 2) router attention (tensor cores): attn fp32 + recv split bf16
    //    m rows = B_*H_ = 512, tiles of 64 -> grid.y = 8  (round-5 bug: was 0)
    router_mma<<<dim3(N_, (B_ * H_) / 64), 128, RSMEM>>>(
        router, qhi, qlo, attn_out, ahi, alo);

    // 3) output = recv @ Wo + bo  (fp32 out)
    transpose_split<<<tgrid, tblk>>>(Wo, wthi, wtlo);
    gemm_mma<<<ggrid, 256, SMEM_SZ>>>(ahi, alo, wthi, wtlo, bo,
                                      out, nullptr, nullptr);
}